// round 9
// baseline (speedup 1.0000x reference)
#include <cuda_runtime.h>
#include <cuda_bf16.h>
#include <cstdint>

#define TT 256
#define NLSTM 128
#define ACHP 18432                 // padded A chunk: 128 rows x 144B
#define SLOTP (16*ACHP)            // per A slot per matrix
#define BCHP 4608                  // padded W chunk: 32 rows x 144B
#define WCTAP (16*BCHP)            // 73728 per CTA per matrix
#define FCDP (16*ACHP)             // FC W d-tile per matrix

// ------------------------- device scratch -------------------------
__device__ __align__(128) unsigned char g_Ahi[(size_t)(TT+1)*SLOTP];
__device__ __align__(128) unsigned char g_Alo[(size_t)(TT+1)*SLOTP];
__device__ __align__(128) unsigned char g_WsHi[(size_t)NLSTM*WCTAP];
__device__ __align__(128) unsigned char g_WsLo[(size_t)NLSTM*WCTAP];
__device__ __align__(128) unsigned char g_W0Hi[(size_t)NLSTM*WCTAP];
__device__ __align__(128) unsigned char g_W0Lo[(size_t)NLSTM*WCTAP];
__device__ __align__(128) unsigned char g_FcHi[(size_t)8*FCDP];
__device__ __align__(128) unsigned char g_FcLo[(size_t)8*FCDP];
__device__ float g_biasP[NLSTM*32];
__device__ unsigned g_cntw[(size_t)(TT+1)*128];   // [t][kc(16)][w(8)] readiness
__device__ unsigned g_bar;
__device__ unsigned g_fcitem;

// ------------------------- helpers -------------------------
__device__ __forceinline__ uint32_t smem_u32(const void* p) {
    uint32_t a;
    asm("{ .reg .u64 t; cvta.to.shared.u64 t, %1; cvt.u32.u64 %0, t; }" : "=r"(a) : "l"(p));
    return a;
}
__device__ __forceinline__ void cpa16(uint32_t dst, const void* src) {
    asm volatile("cp.async.cg.shared.global [%0], [%1], 16;" :: "r"(dst), "l"(src));
}
#define CP_COMMIT() asm volatile("cp.async.commit_group;")
#define CP_WAIT1()  asm volatile("cp.async.wait_group 1;")
#define CP_WAIT0()  asm volatile("cp.async.wait_group 0;")

__device__ __forceinline__ void hmma(float* c, const uint32_t* a, uint32_t b0, uint32_t b1) {
    asm volatile(
        "mma.sync.aligned.m16n8k16.row.col.f32.bf16.bf16.f32 "
        "{%0,%1,%2,%3}, {%4,%5,%6,%7}, {%8,%9}, {%0,%1,%2,%3};"
        : "+f"(c[0]), "+f"(c[1]), "+f"(c[2]), "+f"(c[3])
        : "r"(a[0]), "r"(a[1]), "r"(a[2]), "r"(a[3]), "r"(b0), "r"(b1));
}
__device__ __forceinline__ float sigf(float x)  { return 1.0f / (1.0f + __expf(-x)); }
__device__ __forceinline__ float tanhx(float x) { return 2.0f / (1.0f + __expf(-2.0f * x)) - 1.0f; }

__device__ __forceinline__ void pack8(const float* v, uint4& hi, uint4& lo) {
    __nv_bfloat16 h[8]; float r[8];
#pragma unroll
    for (int e = 0; e < 8; e++) { h[e] = __float2bfloat16(v[e]); r[e] = v[e] - __bfloat162float(h[e]); }
    uint32_t* hw = (uint32_t*)&hi; uint32_t* lw = (uint32_t*)&lo;
#pragma unroll
    for (int q = 0; q < 4; q++) {
        __nv_bfloat162 ph = __halves2bfloat162(h[2*q], h[2*q+1]);
        __nv_bfloat162 pl = __halves2bfloat162(__float2bfloat16(r[2*q]), __float2bfloat16(r[2*q+1]));
        hw[q] = *(uint32_t*)&ph; lw[q] = *(uint32_t*)&pl;
    }
}

// ------------------------- prep -------------------------
__global__ void prep(const float* __restrict__ hT, const float* __restrict__ Wih,
                     const float* __restrict__ Whh, const float* __restrict__ bih,
                     const float* __restrict__ bhh, const float* __restrict__ Wfc)
{
    size_t idx = (size_t)blockIdx.x * blockDim.x + threadIdx.x;
    size_t str = (size_t)gridDim.x * blockDim.x;
    if (idx == 0) { g_bar = 0; g_fcitem = 0; }
    for (size_t i = idx; i < (size_t)(TT+1)*128; i += str) g_cntw[i] = 0;

    for (size_t i = idx; i < (size_t)524288; i += str) {
        int kg = (int)(i & 127), np = (int)((i >> 7) & 31), cta = (int)(i >> 12);
        int row = (np & 3) * 1024 + cta * 8 + (np >> 2);
        int k = kg * 8;
        float wi[8], ws[8];
#pragma unroll
        for (int e = 0; e < 8; e++) {
            float a = Wih[(size_t)row * 1024 + k + e];
            wi[e] = a; ws[e] = a + Whh[(size_t)row * 1024 + k + e];
        }
        size_t base = (size_t)cta * WCTAP + (size_t)(kg >> 3) * BCHP + np * 144 + (kg & 7) * 16;
        uint4 h4, l4;
        pack8(wi, h4, l4);
        *(uint4*)(g_W0Hi + base) = h4; *(uint4*)(g_W0Lo + base) = l4;
        pack8(ws, h4, l4);
        *(uint4*)(g_WsHi + base) = h4; *(uint4*)(g_WsLo + base) = l4;
    }
    for (size_t i = idx; i < (size_t)131072; i += str) {
        int kg = (int)(i & 127), np = (int)((i >> 7) & 127), dt = (int)(i >> 14);
        float w[8];
#pragma unroll
        for (int e = 0; e < 8; e++) w[e] = Wfc[(size_t)(dt * 128 + np) * 1024 + kg * 8 + e];
        size_t base = (size_t)dt * FCDP + (size_t)(kg >> 3) * ACHP + np * 144 + (kg & 7) * 16;
        uint4 h4, l4;
        pack8(w, h4, l4);
        *(uint4*)(g_FcHi + base) = h4; *(uint4*)(g_FcLo + base) = l4;
    }
    for (size_t i = idx; i < (size_t)16384; i += str) {
        int kg = (int)(i & 127), m = (int)(i >> 7);
        float v[8];
#pragma unroll
        for (int e = 0; e < 8; e++) v[e] = hT[(size_t)m * 1024 + kg * 8 + e];
        size_t base = (size_t)(kg >> 3) * ACHP + m * 144 + (kg & 7) * 16;
        uint4 h4, l4;
        pack8(v, h4, l4);
        *(uint4*)(g_Ahi + base) = h4; *(uint4*)(g_Alo + base) = l4;
    }
    for (size_t i = idx; i < (size_t)4096; i += str) {
        int np = (int)(i & 31), cta = (int)(i >> 5);
        int row = (np & 3) * 1024 + cta * 8 + (np >> 2);
        g_biasP[i] = bih[row] + bhh[row];
    }
}

// ------------------------- fused persistent kernel -------------------------
// LSTM smem: [0,73728) Whi resident | [73728,147456) Wlo resident
//   [147456, 221184) per-warp A staging: 8 warps x { 2 bufs x 4608 {Ahi 2304|Alo 2304} }
//   [221184) bias 128B, [221312) item slot
// FC smem (after conversion): 2 buffers x 73728 {Ahi|Alo|Bhi|Blo} in [0,147456)
#define W_LO   73728
#define ABUF   147456
#define WBUF   9216               // per-warp staging (2 x 4608)
#define S_BIAS 221184
#define S_ITEM 221312
#define SM_ALL 221440

__global__ void __launch_bounds__(256, 1) lstm_fused(const float* __restrict__ bfc,
                                                     float* __restrict__ out)
{
    extern __shared__ unsigned char smem[];
    const uint32_t sb = smem_u32(smem);
    const int tid = threadIdx.x;
    const int w = tid >> 5, lane = tid & 31;
    const int g = lane >> 2, tig = lane & 3;
    const int cta = blockIdx.x;

    if (cta < NLSTM) {
        // ---------------- LSTM role ----------------
        if (tid < 32) ((float*)(smem + S_BIAS))[tid] = g_biasP[cta * 32 + tid];
        const float* biasS = (const float*)(smem + S_BIAS);

        // resident W <- W0
        {
            const unsigned char* s2 = g_W0Hi + (size_t)cta * WCTAP;
            const unsigned char* s3 = g_W0Lo + (size_t)cta * WCTAP;
            for (int i = tid; i < 4608; i += 256) cpa16(sb + i * 16, s2 + i * 16);
            for (int i = tid; i < 4608; i += 256) cpa16(sb + W_LO + i * 16, s3 + i * 16);
            CP_COMMIT();
            CP_WAIT0();
        }
        __syncthreads();   // bias + resident W visible to all warps

        float c[4] = {0.f, 0.f, 0.f, 0.f};
        const uint32_t mybuf = sb + ABUF + w * WBUF;      // this warp's staging
        const int rowoff = 16 * w;                        // my A rows: 16w..16w+15
        const unsigned cgrp = (unsigned)(cta >> 3);       // chunk group I produce

        for (int t = 0; t < TT; t++) {
            // my 16 rows of the A slot, hi and lo
            const unsigned char* aH = g_Ahi + (size_t)t * SLOTP + (size_t)rowoff * 144;
            const unsigned char* aL = g_Alo + (size_t)t * SLOTP + (size_t)rowoff * 144;
            const unsigned* cnt = g_cntw + (size_t)t * 128 + w;   // + kc*8

            // wait for chunk kc's producers (warps w of CTAs 8kc..8kc+7), then load
            auto issueA = [&](int kc) {
                if (t > 0) {
                    unsigned v;
                    do {
                        asm volatile("ld.acquire.gpu.global.u32 %0, [%1];"
                                     : "=r"(v) : "l"(cnt + kc * 8));
                        if (v >= 8u) break;
                        __nanosleep(32);
                    } while (1);
                }
                uint32_t d = mybuf + (kc & 1) * 4608;
                const unsigned char* sA = aH + (size_t)kc * ACHP;
                const unsigned char* sL = aL + (size_t)kc * ACHP;
#pragma unroll
                for (int i = 0; i < 5; i++) {
                    int e = lane + i * 32;                // 144 16B-units hi
                    if (e < 144) cpa16(d + e * 16, sA + e * 16);
                }
#pragma unroll
                for (int i = 0; i < 5; i++) {
                    int e = lane + i * 32;                // 144 16B-units lo
                    if (e < 144) cpa16(d + 2304 + e * 16, sL + e * 16);
                }
                CP_COMMIT();
            };

            float accH[4][4], accX[4][4];
#pragma unroll
            for (int n = 0; n < 4; n++)
#pragma unroll
                for (int q = 0; q < 4; q++) { accH[n][q] = 0.f; accX[n][q] = 0.f; }

            issueA(0); issueA(1);
            for (int kc = 0; kc < 16; kc++) {
                if (kc == 15) CP_WAIT0(); else CP_WAIT1();
                __syncwarp();
                const unsigned char* As = smem + ABUF + w * WBUF + (kc & 1) * 4608;
                const unsigned char* Al = As + 2304;
                const unsigned char* Bh = smem + kc * BCHP;
                const unsigned char* Bl = smem + W_LO + kc * BCHP;
                const int rb = g * 144 + tig * 4;         // row g within my 16-row tile
#pragma unroll
                for (int ks = 0; ks < 4; ks++) {
                    const int ao = rb + ks * 32;
                    uint32_t ah[4], al4[4];
                    ah[0] = *(const uint32_t*)(As + ao);
                    ah[1] = *(const uint32_t*)(As + ao + 1152);
                    ah[2] = *(const uint32_t*)(As + ao + 16);
                    ah[3] = *(const uint32_t*)(As + ao + 1168);
                    al4[0] = *(const uint32_t*)(Al + ao);
                    al4[1] = *(const uint32_t*)(Al + ao + 1152);
                    al4[2] = *(const uint32_t*)(Al + ao + 16);
                    al4[3] = *(const uint32_t*)(Al + ao + 1168);
#pragma unroll
                    for (int nt = 0; nt < 4; nt++) {
                        const int bo = (8 * nt + g) * 144 + tig * 4 + ks * 32;
                        uint32_t bh0 = *(const uint32_t*)(Bh + bo);
                        uint32_t bh1 = *(const uint32_t*)(Bh + bo + 16);
                        uint32_t bl0 = *(const uint32_t*)(Bl + bo);
                        uint32_t bl1 = *(const uint32_t*)(Bl + bo + 16);
                        hmma(accH[nt], ah, bh0, bh1);       // depth-1 chain
                        hmma(accX[nt], al4, bh0, bh1);      // depth-2 chain
                        hmma(accX[nt], ah, bl0, bl1);
                    }
                }
                __syncwarp();
                if (kc + 2 < 16) issueA(kc + 2);
            }

            if (t == 0) {
                // all warps must finish reading W0 before the swap
                __syncthreads();
                const unsigned char* s2 = g_WsHi + (size_t)cta * WCTAP;
                const unsigned char* s3 = g_WsLo + (size_t)cta * WCTAP;
                for (int i = tid; i < 4608; i += 256) cpa16(sb + i * 16, s2 + i * 16);
                for (int i = tid; i < 4608; i += 256) cpa16(sb + W_LO + i * 16, s3 + i * 16);
                CP_COMMIT();
                CP_WAIT0();
                __syncthreads();   // whole Wsum visible before step 1 reads it
            }

            // epilogue (warp-local; no block sync)
            const int parity = lane & 1;
#pragma unroll
            for (int nt = 0; nt < 4; nt++) {
                float d0 = accH[nt][0] + accX[nt][0];
                float d1 = accH[nt][1] + accX[nt][1];
                float d2 = accH[nt][2] + accX[nt][2];
                float d3 = accH[nt][3] + accX[nt][3];
                float s0 = parity ? d0 : d2;
                float s1 = parity ? d1 : d3;
                float r0 = __shfl_xor_sync(0xffffffffu, s0, 1);
                float r1 = __shfl_xor_sync(0xffffffffu, s1, 1);
                float ivr, fvr, gvr, ovr; int m;
                if (!parity) { ivr = d0; fvr = d1; gvr = r0; ovr = r1; m = 16 * w + g; }
                else         { ivr = r0; fvr = r1; gvr = d2; ovr = d3; m = 16 * w + g + 8; }
                int u = 2 * nt + (tig >> 1);
                const float* bb = biasS + 4 * u;
                float iv = sigf(ivr + bb[0]);
                float fv = sigf(fvr + bb[1]);
                float gv = tanhx(gvr + bb[2]);
                float ov = sigf(ovr + bb[3]);
                c[nt] = fv * c[nt] + iv * gv;
                float h = ov * tanhx(c[nt]);
                int j = cta * 8 + u;
                size_t off = (size_t)(t + 1) * SLOTP + (size_t)(j >> 6) * ACHP
                           + (size_t)m * 144 + (j & 63) * 2;
                __nv_bfloat16 hh = __float2bfloat16(h);
                *(__nv_bfloat16*)(g_Ahi + off) = hh;
                *(__nv_bfloat16*)(g_Alo + off) = __float2bfloat16(h - __bfloat162float(hh));
            }
            __syncwarp();
            if (lane == 0) {
                unsigned* cp = g_cntw + (size_t)(t + 1) * 128 + cgrp * 8 + w;
                asm volatile("red.release.gpu.global.add.u32 [%0], %1;" :: "l"(cp), "r"(1u) : "memory");
                asm volatile("red.release.gpu.global.add.u32 [%0], %1;" :: "l"(&g_bar), "r"(1u) : "memory");
            }
        }
        __syncthreads();
    }

    // ---------------- FC worker role (all CTAs end up here) ----------------
    unsigned* itemp = (unsigned*)(smem + S_ITEM);
    for (;;) {
        __syncthreads();
        if (tid == 0) *itemp = atomicAdd(&g_fcitem, 1u);
        __syncthreads();
        unsigned item = *itemp;
        if (item >= 2048u) break;
        int s = (int)(item >> 3), dt = (int)(item & 7);

        if (tid == 0) {
            unsigned tgt = (unsigned)(NLSTM * 8 * (s + 1)), v;   // 1024 warp-arrivals per step
            do {
                asm volatile("ld.acquire.gpu.global.u32 %0, [%1];" : "=r"(v) : "l"(&g_bar));
                if ((int)(v - tgt) >= 0) break;
                __nanosleep(64);
            } while (1);
        }
        __syncthreads();

        const unsigned char* aH = g_Ahi + (size_t)(s + 1) * SLOTP;
        const unsigned char* aL = g_Alo + (size_t)(s + 1) * SLOTP;
        const unsigned char* bH = g_FcHi + (size_t)dt * FCDP;
        const unsigned char* bL = g_FcLo + (size_t)dt * FCDP;

        auto issueF = [&](int kc) {
            uint32_t d = sb + (kc & 1) * 73728;
            const unsigned char* s0 = aH + (size_t)kc * ACHP;
            const unsigned char* s1 = aL + (size_t)kc * ACHP;
            const unsigned char* s2 = bH + (size_t)kc * ACHP;
            const unsigned char* s3 = bL + (size_t)kc * ACHP;
            for (int i = tid; i < 1152; i += 256) cpa16(d + i * 16, s0 + i * 16);
            for (int i = tid; i < 1152; i += 256) cpa16(d + 18432 + i * 16, s1 + i * 16);
            for (int i = tid; i < 1152; i += 256) cpa16(d + 36864 + i * 16, s2 + i * 16);
            for (int i = tid; i < 1152; i += 256) cpa16(d + 55296 + i * 16, s3 + i * 16);
            CP_COMMIT();
        };

        float acc[16][4];
#pragma unroll
        for (int n = 0; n < 16; n++)
#pragma unroll
            for (int q = 0; q < 4; q++) acc[n][q] = 0.f;

        issueF(0); issueF(1);
        for (int kc = 0; kc < 16; kc++) {
            if (kc == 15) CP_WAIT0(); else CP_WAIT1();
            __syncthreads();
            const unsigned char* As = smem + (kc & 1) * 73728;
            const unsigned char* Al = As + 18432;
            const unsigned char* Bh = As + 36864;
            const unsigned char* Bl = As + 55296;
            const int rb = (16 * w + g) * 144 + tig * 4;
#pragma unroll
            for (int ks = 0; ks < 4; ks++) {
                const int ao = rb + ks * 32;
                uint32_t ah[4], al4[4];
                ah[0] = *(const uint32_t*)(As + ao);
                ah[1] = *(const uint32_t*)(As + ao + 1152);
                ah[2] = *(const uint32_t*)(As + ao + 16);
                ah[3] = *(const uint32_t*)(As + ao + 1168);
                al4[0] = *(const uint32_t*)(Al + ao);
                al4[1] = *(const uint32_t*)(Al + ao + 1152);
                al4[2] = *(const uint32_t*)(Al + ao + 16);
                al4[3] = *(const uint32_t*)(Al + ao + 1168);
#pragma unroll
                for (int nt = 0; nt < 16; nt++) {
                    const int bo = (8 * nt + g) * 144 + tig * 4 + ks * 32;
                    uint32_t bh0 = *(const uint32_t*)(Bh + bo);
                    uint32_t bh1 = *(const uint32_t*)(Bh + bo + 16);
                    uint32_t bl0 = *(const uint32_t*)(Bl + bo);
                    uint32_t bl1 = *(const uint32_t*)(Bl + bo + 16);
                    hmma(acc[nt], ah, bh0, bh1);
                    hmma(acc[nt], al4, bh0, bh1);
                    hmma(acc[nt], ah, bl0, bl1);
                }
            }
            __syncthreads();
            if (kc + 2 < 16) issueF(kc + 2);
        }

#pragma unroll
        for (int nt = 0; nt < 16; nt++) {
            int d = dt * 128 + 8 * nt + 2 * tig;
            float2 bb = *(const float2*)(bfc + d);
            int n0 = 16 * w + g;
            float2 v0 = make_float2(acc[nt][0] + bb.x, acc[nt][1] + bb.y);
            float2 v1 = make_float2(acc[nt][2] + bb.x, acc[nt][3] + bb.y);
            *(float2*)(out + ((size_t)n0 * TT + s) * 1024 + d) = v0;
            *(float2*)(out + ((size_t)(n0 + 8) * TT + s) * 1024 + d) = v1;
        }
    }
}

// ------------------------- launch -------------------------
extern "C" void kernel_launch(void* const* d_in, const int* in_sizes, int n_in,
                              void* d_out, int out_size)
{
    const float* hT  = (const float*)d_in[0];
    const float* Wih = (const float*)d_in[1];
    const float* Whh = (const float*)d_in[2];
    const float* bih = (const float*)d_in[3];
    const float* bhh = (const float*)d_in[4];
    const float* Wfc = (const float*)d_in[5];
    const float* bfc = (const float*)d_in[6];
    float* out = (float*)d_out;

    static int total = 0;
    if (total == 0) {
        int smc = 148;
        if (cudaDeviceGetAttribute(&smc, cudaDevAttrMultiProcessorCount, 0) != cudaSuccess)
            smc = 148;
        total = smc < 129 ? 129 : (smc > 192 ? 192 : smc);
        cudaFuncSetAttribute(lstm_fused, cudaFuncAttributeMaxDynamicSharedMemorySize, SM_ALL);
    }

    prep<<<1024, 256>>>(hT, Wih, Whh, bih, bhh, Wfc);
    lstm_fused<<<total, 256, SM_ALL>>>(bfc, out);
}

// round 11
// speedup vs baseline: 1.1359x; 1.1359x over previous
#include <cuda_runtime.h>
#include <cuda_bf16.h>
#include <cstdint>

#define TT 256
#define NLSTM 128
#define ACHP 18432                 // padded A chunk: 128 rows x 144B
#define SLOTP (16*ACHP)            // per A slot per matrix
#define BCHP 4608                  // padded W chunk: 32 rows x 144B
#define WCTAP (16*BCHP)            // 73728 per CTA per matrix
#define FCDP (16*ACHP)             // FC W d-tile per matrix

// ------------------------- device scratch -------------------------
__device__ __align__(128) unsigned char g_Ahi[(size_t)(TT+1)*SLOTP];
__device__ __align__(128) unsigned char g_Alo[(size_t)(TT+1)*SLOTP];
__device__ __align__(128) unsigned char g_WsHi[(size_t)NLSTM*WCTAP];
__device__ __align__(128) unsigned char g_WsLo[(size_t)NLSTM*WCTAP];
__device__ __align__(128) unsigned char g_W0Hi[(size_t)NLSTM*WCTAP];
__device__ __align__(128) unsigned char g_W0Lo[(size_t)NLSTM*WCTAP];
__device__ __align__(128) unsigned char g_FcHi[(size_t)8*FCDP];
__device__ __align__(128) unsigned char g_FcLo[(size_t)8*FCDP];
__device__ float g_biasP[NLSTM*32];
__device__ unsigned g_cw[(size_t)(TT+1)*8];   // [t][w] row-band readiness (target 128)
__device__ unsigned g_bar;                    // warp-grain step counter (FC gating)
__device__ unsigned g_fcitem;

// ------------------------- helpers -------------------------
__device__ __forceinline__ uint32_t smem_u32(const void* p) {
    uint32_t a;
    asm("{ .reg .u64 t; cvta.to.shared.u64 t, %1; cvt.u32.u64 %0, t; }" : "=r"(a) : "l"(p));
    return a;
}
__device__ __forceinline__ void cpa16(uint32_t dst, const void* src) {
    asm volatile("cp.async.cg.shared.global [%0], [%1], 16;" :: "r"(dst), "l"(src));
}
#define CP_COMMIT() asm volatile("cp.async.commit_group;")
#define CP_WAIT1()  asm volatile("cp.async.wait_group 1;")
#define CP_WAIT0()  asm volatile("cp.async.wait_group 0;")

__device__ __forceinline__ void hmma(float* c, const uint32_t* a, uint32_t b0, uint32_t b1) {
    asm volatile(
        "mma.sync.aligned.m16n8k16.row.col.f32.bf16.bf16.f32 "
        "{%0,%1,%2,%3}, {%4,%5,%6,%7}, {%8,%9}, {%0,%1,%2,%3};"
        : "+f"(c[0]), "+f"(c[1]), "+f"(c[2]), "+f"(c[3])
        : "r"(a[0]), "r"(a[1]), "r"(a[2]), "r"(a[3]), "r"(b0), "r"(b1));
}
__device__ __forceinline__ float sigf(float x)  { return 1.0f / (1.0f + __expf(-x)); }
__device__ __forceinline__ float tanhx(float x) { return 2.0f / (1.0f + __expf(-2.0f * x)) - 1.0f; }

__device__ __forceinline__ void pack8(const float* v, uint4& hi, uint4& lo) {
    __nv_bfloat16 h[8]; float r[8];
#pragma unroll
    for (int e = 0; e < 8; e++) { h[e] = __float2bfloat16(v[e]); r[e] = v[e] - __bfloat162float(h[e]); }
    uint32_t* hw = (uint32_t*)&hi; uint32_t* lw = (uint32_t*)&lo;
#pragma unroll
    for (int q = 0; q < 4; q++) {
        __nv_bfloat162 ph = __halves2bfloat162(h[2*q], h[2*q+1]);
        __nv_bfloat162 pl = __halves2bfloat162(__float2bfloat16(r[2*q]), __float2bfloat16(r[2*q+1]));
        hw[q] = *(uint32_t*)&ph; lw[q] = *(uint32_t*)&pl;
    }
}

// ------------------------- prep -------------------------
__global__ void prep(const float* __restrict__ hT, const float* __restrict__ Wih,
                     const float* __restrict__ Whh, const float* __restrict__ bih,
                     const float* __restrict__ bhh, const float* __restrict__ Wfc)
{
    size_t idx = (size_t)blockIdx.x * blockDim.x + threadIdx.x;
    size_t str = (size_t)gridDim.x * blockDim.x;
    if (idx == 0) { g_bar = 0; g_fcitem = 0; }
    for (size_t i = idx; i < (size_t)(TT+1)*8; i += str) g_cw[i] = 0;

    for (size_t i = idx; i < (size_t)524288; i += str) {
        int kg = (int)(i & 127), np = (int)((i >> 7) & 31), cta = (int)(i >> 12);
        int row = (np & 3) * 1024 + cta * 8 + (np >> 2);
        int k = kg * 8;
        float wi[8], ws[8];
#pragma unroll
        for (int e = 0; e < 8; e++) {
            float a = Wih[(size_t)row * 1024 + k + e];
            wi[e] = a; ws[e] = a + Whh[(size_t)row * 1024 + k + e];
        }
        size_t base = (size_t)cta * WCTAP + (size_t)(kg >> 3) * BCHP + np * 144 + (kg & 7) * 16;
        uint4 h4, l4;
        pack8(wi, h4, l4);
        *(uint4*)(g_W0Hi + base) = h4; *(uint4*)(g_W0Lo + base) = l4;
        pack8(ws, h4, l4);
        *(uint4*)(g_WsHi + base) = h4; *(uint4*)(g_WsLo + base) = l4;
    }
    for (size_t i = idx; i < (size_t)131072; i += str) {
        int kg = (int)(i & 127), np = (int)((i >> 7) & 127), dt = (int)(i >> 14);
        float w[8];
#pragma unroll
        for (int e = 0; e < 8; e++) w[e] = Wfc[(size_t)(dt * 128 + np) * 1024 + kg * 8 + e];
        size_t base = (size_t)dt * FCDP + (size_t)(kg >> 3) * ACHP + np * 144 + (kg & 7) * 16;
        uint4 h4, l4;
        pack8(w, h4, l4);
        *(uint4*)(g_FcHi + base) = h4; *(uint4*)(g_FcLo + base) = l4;
    }
    for (size_t i = idx; i < (size_t)16384; i += str) {
        int kg = (int)(i & 127), m = (int)(i >> 7);
        float v[8];
#pragma unroll
        for (int e = 0; e < 8; e++) v[e] = hT[(size_t)m * 1024 + kg * 8 + e];
        size_t base = (size_t)(kg >> 3) * ACHP + m * 144 + (kg & 7) * 16;
        uint4 h4, l4;
        pack8(v, h4, l4);
        *(uint4*)(g_Ahi + base) = h4; *(uint4*)(g_Alo + base) = l4;
    }
    for (size_t i = idx; i < (size_t)4096; i += str) {
        int np = (int)(i & 31), cta = (int)(i >> 5);
        int row = (np & 3) * 1024 + cta * 8 + (np >> 2);
        g_biasP[i] = bih[row] + bhh[row];
    }
}

// ------------------------- fused persistent kernel -------------------------
// LSTM smem: [0,73728) Whi resident | [73728,147456) Wlo resident
//   [147456, 221184) per-warp A staging: 8 warps x { 2 bufs x 4608 {Ahi 2304|Alo 2304} }
//   [221184) bias 128B, [221312) item slot
// FC smem (after conversion): 2 buffers x 73728 {Ahi|Alo|Bhi|Blo} in [0,147456)
#define W_LO   73728
#define ABUF   147456
#define WBUF   9216               // per-warp staging (2 x 4608)
#define S_BIAS 221184
#define S_ITEM 221312
#define SM_ALL 221440

__global__ void __launch_bounds__(256, 1) lstm_fused(const float* __restrict__ bfc,
                                                     float* __restrict__ out)
{
    extern __shared__ unsigned char smem[];
    const uint32_t sb = smem_u32(smem);
    const int tid = threadIdx.x;
    const int w = tid >> 5, lane = tid & 31;
    const int g = lane >> 2, tig = lane & 3;
    const int cta = blockIdx.x;

    if (cta < NLSTM) {
        // ---------------- LSTM role ----------------
        if (tid < 32) ((float*)(smem + S_BIAS))[tid] = g_biasP[cta * 32 + tid];
        const float* biasS = (const float*)(smem + S_BIAS);

        // resident W <- W0
        {
            const unsigned char* s2 = g_W0Hi + (size_t)cta * WCTAP;
            const unsigned char* s3 = g_W0Lo + (size_t)cta * WCTAP;
            for (int i = tid; i < 4608; i += 256) cpa16(sb + i * 16, s2 + i * 16);
            for (int i = tid; i < 4608; i += 256) cpa16(sb + W_LO + i * 16, s3 + i * 16);
            CP_COMMIT();
            CP_WAIT0();
        }
        __syncthreads();   // bias + resident W visible to all warps

        float c[4] = {0.f, 0.f, 0.f, 0.f};
        const uint32_t mybuf = sb + ABUF + w * WBUF;      // this warp's staging
        const int rowoff = 16 * w;                        // my A rows: 16w..16w+15

        for (int t = 0; t < TT; t++) {
            // row-band barrier: need warp w of ALL 128 CTAs done producing slot t.
            // ALL lanes run the acquire poll (R9-proven primitive): each lane's
            // own acquire orders its subsequent cp.async reads. lane0-only +
            // syncwarp was NOT sufficient (R10 failure).
            if (t > 0) {
                const unsigned* cp = g_cw + (size_t)t * 8 + w;
                unsigned v;
                do {
                    asm volatile("ld.acquire.gpu.global.u32 %0, [%1];" : "=r"(v) : "l"(cp));
                    if (v >= 128u) break;
                    __nanosleep(32);
                } while (1);
            }
            __syncwarp();

            // my 16 rows of the A slot, hi and lo
            const unsigned char* aH = g_Ahi + (size_t)t * SLOTP + (size_t)rowoff * 144;
            const unsigned char* aL = g_Alo + (size_t)t * SLOTP + (size_t)rowoff * 144;

            auto issueA = [&](int kc) {
                uint32_t d = mybuf + (kc & 1) * 4608;
                const unsigned char* sA = aH + (size_t)kc * ACHP;
                const unsigned char* sL = aL + (size_t)kc * ACHP;
#pragma unroll
                for (int i = 0; i < 5; i++) {
                    int e = lane + i * 32;                // 144 16B-units hi
                    if (e < 144) cpa16(d + e * 16, sA + e * 16);
                }
#pragma unroll
                for (int i = 0; i < 5; i++) {
                    int e = lane + i * 32;                // 144 16B-units lo
                    if (e < 144) cpa16(d + 2304 + e * 16, sL + e * 16);
                }
                CP_COMMIT();
            };

            float accH[4][4], accX[4][4];
#pragma unroll
            for (int n = 0; n < 4; n++)
#pragma unroll
                for (int q = 0; q < 4; q++) { accH[n][q] = 0.f; accX[n][q] = 0.f; }

            issueA(0); issueA(1);
            for (int kc = 0; kc < 16; kc++) {
                if (kc == 15) CP_WAIT0(); else CP_WAIT1();
                __syncwarp();
                const unsigned char* As = smem + ABUF + w * WBUF + (kc & 1) * 4608;
                const unsigned char* Al = As + 2304;
                const unsigned char* Bh = smem + kc * BCHP;
                const unsigned char* Bl = smem + W_LO + kc * BCHP;
                const int rb = g * 144 + tig * 4;         // row g within my 16-row tile
#pragma unroll
                for (int ks = 0; ks < 4; ks++) {
                    const int ao = rb + ks * 32;
                    uint32_t ah[4], al4[4];
                    ah[0] = *(const uint32_t*)(As + ao);
                    ah[1] = *(const uint32_t*)(As + ao + 1152);
                    ah[2] = *(const uint32_t*)(As + ao + 16);
                    ah[3] = *(const uint32_t*)(As + ao + 1168);
                    al4[0] = *(const uint32_t*)(Al + ao);
                    al4[1] = *(const uint32_t*)(Al + ao + 1152);
                    al4[2] = *(const uint32_t*)(Al + ao + 16);
                    al4[3] = *(const uint32_t*)(Al + ao + 1168);
#pragma unroll
                    for (int nt = 0; nt < 4; nt++) {
                        const int bo = (8 * nt + g) * 144 + tig * 4 + ks * 32;
                        uint32_t bh0 = *(const uint32_t*)(Bh + bo);
                        uint32_t bh1 = *(const uint32_t*)(Bh + bo + 16);
                        uint32_t bl0 = *(const uint32_t*)(Bl + bo);
                        uint32_t bl1 = *(const uint32_t*)(Bl + bo + 16);
                        hmma(accH[nt], ah, bh0, bh1);       // depth-1 chain
                        hmma(accX[nt], al4, bh0, bh1);      // depth-2 chain
                        hmma(accX[nt], ah, bl0, bl1);
                    }
                }
                __syncwarp();
                if (kc + 2 < 16) issueA(kc + 2);
            }

            if (t == 0) {
                // all warps must finish reading W0 before the swap
                __syncthreads();
                const unsigned char* s2 = g_WsHi + (size_t)cta * WCTAP;
                const unsigned char* s3 = g_WsLo + (size_t)cta * WCTAP;
                for (int i = tid; i < 4608; i += 256) cpa16(sb + i * 16, s2 + i * 16);
                for (int i = tid; i < 4608; i += 256) cpa16(sb + W_LO + i * 16, s3 + i * 16);
                CP_COMMIT();
                CP_WAIT0();
                __syncthreads();   // whole Wsum visible before step 1 reads it
            }

            // epilogue (warp-local)
            const int parity = lane & 1;
#pragma unroll
            for (int nt = 0; nt < 4; nt++) {
                float d0 = accH[nt][0] + accX[nt][0];
                float d1 = accH[nt][1] + accX[nt][1];
                float d2 = accH[nt][2] + accX[nt][2];
                float d3 = accH[nt][3] + accX[nt][3];
                float s0 = parity ? d0 : d2;
                float s1 = parity ? d1 : d3;
                float r0 = __shfl_xor_sync(0xffffffffu, s0, 1);
                float r1 = __shfl_xor_sync(0xffffffffu, s1, 1);
                float ivr, fvr, gvr, ovr; int m;
                if (!parity) { ivr = d0; fvr = d1; gvr = r0; ovr = r1; m = 16 * w + g; }
                else         { ivr = r0; fvr = r1; gvr = d2; ovr = d3; m = 16 * w + g + 8; }
                int u = 2 * nt + (tig >> 1);
                const float* bb = biasS + 4 * u;
                float iv = sigf(ivr + bb[0]);
                float fv = sigf(fvr + bb[1]);
                float gv = tanhx(gvr + bb[2]);
                float ov = sigf(ovr + bb[3]);
                c[nt] = fv * c[nt] + iv * gv;
                float h = ov * tanhx(c[nt]);
                int j = cta * 8 + u;
                size_t off = (size_t)(t + 1) * SLOTP + (size_t)(j >> 6) * ACHP
                           + (size_t)m * 144 + (j & 63) * 2;
                __nv_bfloat16 hh = __float2bfloat16(h);
                *(__nv_bfloat16*)(g_Ahi + off) = hh;
                *(__nv_bfloat16*)(g_Alo + off) = __float2bfloat16(h - __bfloat162float(hh));
            }
            __syncwarp();      // all lanes' stores ordered before the release
            if (lane == 0) {
                unsigned* cp = g_cw + (size_t)(t + 1) * 8 + w;
                asm volatile("red.release.gpu.global.add.u32 [%0], %1;" :: "l"(cp), "r"(1u) : "memory");
                asm volatile("red.release.gpu.global.add.u32 [%0], %1;" :: "l"(&g_bar), "r"(1u) : "memory");
            }
        }
        __syncthreads();
    }

    // ---------------- FC worker role (all CTAs end up here) ----------------
    unsigned* itemp = (unsigned*)(smem + S_ITEM);
    for (;;) {
        __syncthreads();
        if (tid == 0) *itemp = atomicAdd(&g_fcitem, 1u);
        __syncthreads();
        unsigned item = *itemp;
        if (item >= 2048u) break;
        int s = (int)(item >> 3), dt = (int)(item & 7);

        // ALL threads poll (same acquire-per-reader principle as the LSTM gate)
        {
            unsigned tgt = (unsigned)(NLSTM * 8 * (s + 1)), v;   // 1024 warp-arrivals/step
            do {
                asm volatile("ld.acquire.gpu.global.u32 %0, [%1];" : "=r"(v) : "l"(&g_bar));
                if ((int)(v - tgt) >= 0) break;
                __nanosleep(64);
            } while (1);
        }
        __syncthreads();

        const unsigned char* aH = g_Ahi + (size_t)(s + 1) * SLOTP;
        const unsigned char* aL = g_Alo + (size_t)(s + 1) * SLOTP;
        const unsigned char* bH = g_FcHi + (size_t)dt * FCDP;
        const unsigned char* bL = g_FcLo + (size_t)dt * FCDP;

        auto issueF = [&](int kc) {
            uint32_t d = sb + (kc & 1) * 73728;
            const unsigned char* s0 = aH + (size_t)kc * ACHP;
            const unsigned char* s1 = aL + (size_t)kc * ACHP;
            const unsigned char* s2 = bH + (size_t)kc * ACHP;
            const unsigned char* s3 = bL + (size_t)kc * ACHP;
            for (int i = tid; i < 1152; i += 256) cpa16(d + i * 16, s0 + i * 16);
            for (int i = tid; i < 1152; i += 256) cpa16(d + 18432 + i * 16, s1 + i * 16);
            for (int i = tid; i < 1152; i += 256) cpa16(d + 36864 + i * 16, s2 + i * 16);
            for (int i = tid; i < 1152; i += 256) cpa16(d + 55296 + i * 16, s3 + i * 16);
            CP_COMMIT();
        };

        float acc[16][4];
#pragma unroll
        for (int n = 0; n < 16; n++)
#pragma unroll
            for (int q = 0; q < 4; q++) acc[n][q] = 0.f;

        issueF(0); issueF(1);
        for (int kc = 0; kc < 16; kc++) {
            if (kc == 15) CP_WAIT0(); else CP_WAIT1();
            __syncthreads();
            const unsigned char* As = smem + (kc & 1) * 73728;
            const unsigned char* Al = As + 18432;
            const unsigned char* Bh = As + 36864;
            const unsigned char* Bl = As + 55296;
            const int rb = (16 * w + g) * 144 + tig * 4;
#pragma unroll
            for (int ks = 0; ks < 4; ks++) {
                const int ao = rb + ks * 32;
                uint32_t ah[4], al4[4];
                ah[0] = *(const uint32_t*)(As + ao);
                ah[1] = *(const uint32_t*)(As + ao + 1152);
                ah[2] = *(const uint32_t*)(As + ao + 16);
                ah[3] = *(const uint32_t*)(As + ao + 1168);
                al4[0] = *(const uint32_t*)(Al + ao);
                al4[1] = *(const uint32_t*)(Al + ao + 1152);
                al4[2] = *(const uint32_t*)(Al + ao + 16);
                al4[3] = *(const uint32_t*)(Al + ao + 1168);
#pragma unroll
                for (int nt = 0; nt < 16; nt++) {
                    const int bo = (8 * nt + g) * 144 + tig * 4 + ks * 32;
                    uint32_t bh0 = *(const uint32_t*)(Bh + bo);
                    uint32_t bh1 = *(const uint32_t*)(Bh + bo + 16);
                    uint32_t bl0 = *(const uint32_t*)(Bl + bo);
                    uint32_t bl1 = *(const uint32_t*)(Bl + bo + 16);
                    hmma(acc[nt], ah, bh0, bh1);
                    hmma(acc[nt], al4, bh0, bh1);
                    hmma(acc[nt], ah, bl0, bl1);
                }
            }
            __syncthreads();
            if (kc + 2 < 16) issueF(kc + 2);
        }

#pragma unroll
        for (int nt = 0; nt < 16; nt++) {
            int d = dt * 128 + 8 * nt + 2 * tig;
            float2 bb = *(const float2*)(bfc + d);
            int n0 = 16 * w + g;
            float2 v0 = make_float2(acc[nt][0] + bb.x, acc[nt][1] + bb.y);
            float2 v1 = make_float2(acc[nt][2] + bb.x, acc[nt][3] + bb.y);
            *(float2*)(out + ((size_t)n0 * TT + s) * 1024 + d) = v0;
            *(float2*)(out + ((size_t)(n0 + 8) * TT + s) * 1024 + d) = v1;
        }
    }
}

// ------------------------- launch -------------------------
extern "C" void kernel_launch(void* const* d_in, const int* in_sizes, int n_in,
                              void* d_out, int out_size)
{
    const float* hT  = (const float*)d_in[0];
    const float* Wih = (const float*)d_in[1];
    const float* Whh = (const float*)d_in[2];
    const float* bih = (const float*)d_in[3];
    const float* bhh = (const float*)d_in[4];
    const float* Wfc = (const float*)d_in[5];
    const float* bfc = (const float*)d_in[6];
    float* out = (float*)d_out;

    static int total = 0;
    if (total == 0) {
        int smc = 148;
        if (cudaDeviceGetAttribute(&smc, cudaDevAttrMultiProcessorCount, 0) != cudaSuccess)
            smc = 148;
        total = smc < 129 ? 129 : (smc > 192 ? 192 : smc);
        cudaFuncSetAttribute(lstm_fused, cudaFuncAttributeMaxDynamicSharedMemorySize, SM_ALL);
    }

    prep<<<1024, 256>>>(hT, Wih, Whh, bih, bhh, Wfc);
    lstm_fused<<<total, 256, SM_ALL>>>(bfc, out);
}